// round 9
// baseline (speedup 1.0000x reference)
#include <cuda_runtime.h>
#include <cstddef>

// Problem constants
#define SQ   512      // sequence length S
#define ED   512      // embedding dim E
#define HD   512      // hidden dim H
#define G4   2048     // 4*H gates
#define BSEL 63       // only batch sample 63 reaches the output
#define NVOC 32000

#define NCTA 64       // scan CTAs; each owns 8 h elements
#define TPB  512      // 16 warps: 8 compute + 8 poller

// Scratch (device globals; no allocation allowed)
__device__ float g_hist[SQ * HD];    // published h+2.0 per (t, element); 0 = not ready. 1 MB
__device__ float g_xg[SQ * G4];      // xg TRANSPOSED: [t][element][gate], 4 MB
__device__ int   g_tok[SQ];          // batch-63 tokens, dtype-normalized

// ---------------------------------------------------------------------------
// Kernel 0a: zero the history buffer so graph replays are deterministic.
// ---------------------------------------------------------------------------
__global__ void zero_hist_kernel() {
    int idx = blockIdx.x * blockDim.x + threadIdx.x;
    int stride = gridDim.x * blockDim.x;
    for (int i = idx; i < SQ * HD; i += stride) g_hist[i] = 0.f;
}

// ---------------------------------------------------------------------------
// Kernel 0b: normalize token dtype (int32 vs int64) and extract batch 63.
// ---------------------------------------------------------------------------
__global__ void __launch_bounds__(SQ) token_prep_kernel(const int* __restrict__ raw) {
    __shared__ int any_nz;
    const int tid = threadIdx.x;            // 0..511
    if (tid == 0) any_nz = 0;
    __syncthreads();
    if (tid < 256 && raw[2 * tid + 1] != 0) atomicExch(&any_nz, 1);
    __syncthreads();
    const bool is64 = (any_nz == 0);
    const long long idx = (long long)BSEL * SQ + tid;
    int tok = is64 ? raw[2 * idx] : raw[idx];
    tok = min(max(tok, 0), NVOC - 1);       // never IMA, even on dtype surprise
    g_tok[tid] = tok;
}

// ---------------------------------------------------------------------------
// Kernel 1: xg GEMM, output TRANSPOSED to [t][element][gate].
// ---------------------------------------------------------------------------
#define BM 64
#define BN 64
#define BK 16

__global__ void __launch_bounds__(256) xg_gemm_kernel(
    const float* __restrict__ emb,
    const float* __restrict__ Wih,
    const float* __restrict__ bih,
    const float* __restrict__ bhh)
{
    __shared__ float As[BK][BM];
    __shared__ float Bs[BK][BN];
    __shared__ int   toks[BM];

    const int bs = blockIdx.x * BM;   // s base
    const int bg = blockIdx.y * BN;   // g base
    const int tid = threadIdx.x;

    if (tid < BM) toks[tid] = g_tok[bs + tid];
    __syncthreads();

    const int tm = (tid >> 4) << 2;   // 0,4,...,60
    const int tn = (tid & 15) << 2;   // 0,4,...,60

    float acc[4][4];
    #pragma unroll
    for (int i = 0; i < 4; i++)
        #pragma unroll
        for (int j = 0; j < 4; j++) acc[i][j] = 0.f;

    for (int k0 = 0; k0 < ED; k0 += BK) {
        #pragma unroll
        for (int i = tid; i < BM * BK; i += 256) {
            int m = i >> 4, k = i & 15;
            As[k][m] = emb[(size_t)toks[m] * ED + k0 + k];
        }
        #pragma unroll
        for (int i = tid; i < BN * BK; i += 256) {
            int n = i >> 4, k = i & 15;
            Bs[k][n] = Wih[(size_t)(bg + n) * ED + k0 + k];
        }
        __syncthreads();
        #pragma unroll
        for (int k = 0; k < BK; k++) {
            float4 a = *(const float4*)&As[k][tm];
            float4 b = *(const float4*)&Bs[k][tn];
            float av[4] = {a.x, a.y, a.z, a.w};
            float bv[4] = {b.x, b.y, b.z, b.w};
            #pragma unroll
            for (int i = 0; i < 4; i++)
                #pragma unroll
                for (int j = 0; j < 4; j++)
                    acc[i][j] = fmaf(av[i], bv[j], acc[i][j]);
        }
        __syncthreads();
    }

    #pragma unroll
    for (int i = 0; i < 4; i++) {
        int s = bs + tm + i;
        #pragma unroll
        for (int j = 0; j < 4; j++) {
            int g = bg + tn + j;
            int e = g & (HD - 1), q = g >> 9;
            g_xg[(size_t)s * G4 + (e << 2) + q] = acc[i][j] + bih[g] + bhh[g];
        }
    }
}

// ---------------------------------------------------------------------------
// Kernel 2: persistent LSTM scan, batch element 63 only.
// 64 CTAs x 512 threads. Warp-specialized:
//   warps 0-7  (computers): warp w owns element hi=8*cta+w; computes all 4
//       gate dots (weights in 64 regs/lane), butterfly-reduces, lane 0 does
//       activations, publishes h+2 to g_hist[t] AND writes own h into the
//       next-parity smem buffer (own-CTA bypass of the L2 round trip).
//   warps 8-15 (pollers): during iteration t they spin on g_hist[t] (v2/lane,
//       both words from the SAME producer CTA; own-CTA words skipped) and
//       stage h-2 into h_sm[(t+1)&1] — detection overlaps compute.
// ONE __syncthreads per step closes the cycle.
// ---------------------------------------------------------------------------
__device__ __forceinline__ float sigmoidf_(float x) {
    return __fdividef(1.f, 1.f + __expf(-x));
}
__device__ __forceinline__ float tanhf_(float x) {
    x = fminf(fmaxf(x, -15.f), 15.f);
    float e = __expf(2.f * x);
    return __fdividef(e - 1.f, e + 1.f);
}

__global__ void __launch_bounds__(TPB, 1) lstm_scan_kernel(
    const float* __restrict__ h0,
    const float* __restrict__ c0,
    const float* __restrict__ Whh)
{
    __shared__ float h_sm[2][HD];       // parity double-buffered h (4 KB)

    const int cta = blockIdx.x;         // 0..63
    const int tid = threadIdx.x;
    const int w = tid >> 5;             // warp 0..15
    const int l = tid & 31;

    // ---- compute-warp setup (warps 0-7) ----
    const int hi = (cta << 3) + w;      // owned global element (valid for w<8)
    float wt[4][16];                    // 4 gate rows of W_hh, 16 elems/lane
    if (w < 8) {
        #pragma unroll
        for (int q = 0; q < 4; q++) {
            const float* row = Whh + ((size_t)((q << 9) + hi) << 9);
            #pragma unroll
            for (int a = 0; a < 4; a++) {
                float4 v = *(const float4*)&row[(a << 7) + (l << 2)];
                wt[q][a * 4 + 0] = v.x; wt[q][a * 4 + 1] = v.y;
                wt[q][a * 4 + 2] = v.z; wt[q][a * 4 + 3] = v.w;
            }
        }
    }
    float creg = 0.f;
    if (w < 8 && l == 0) creg = c0[(size_t)BSEL * HD + hi];

    // ---- poller-warp setup (warps 8-15) ----
    const int j = w - 8;                        // 0..7
    const int widx = (j << 6) + (l << 1);       // this lane's 2 words
    const bool mine = ((widx >> 3) == cta);     // produced by own CTA -> skip

    // Seed h_sm[0] with h0[0, 63, :]
    h_sm[0][tid] = h0[(size_t)BSEL * HD + tid];
    __syncthreads();

    for (int t = 0; t < SQ; t++) {
        if (w < 8) {
            // ------------------ computer ------------------
            float4 xg4 = make_float4(0.f, 0.f, 0.f, 0.f);
            if (l == 0)
                xg4 = *(const float4*)&g_xg[((size_t)t << 11) + (hi << 2)];

            const float* hb = h_sm[t & 1];
            float hreg[16];
            #pragma unroll
            for (int a = 0; a < 4; a++) {
                float4 v = *(const float4*)&hb[(a << 7) + (l << 2)];
                hreg[a * 4 + 0] = v.x; hreg[a * 4 + 1] = v.y;
                hreg[a * 4 + 2] = v.z; hreg[a * 4 + 3] = v.w;
            }
            float s0 = 0.f, s1 = 0.f, s2 = 0.f, s3 = 0.f;
            #pragma unroll
            for (int i = 0; i < 16; i++) {
                s0 = fmaf(wt[0][i], hreg[i], s0);
                s1 = fmaf(wt[1][i], hreg[i], s1);
                s2 = fmaf(wt[2][i], hreg[i], s2);
                s3 = fmaf(wt[3][i], hreg[i], s3);
            }
            #pragma unroll
            for (int off = 16; off; off >>= 1) {
                s0 += __shfl_xor_sync(0xffffffffu, s0, off);
                s1 += __shfl_xor_sync(0xffffffffu, s1, off);
                s2 += __shfl_xor_sync(0xffffffffu, s2, off);
                s3 += __shfl_xor_sync(0xffffffffu, s3, off);
            }
            if (l == 0) {
                float iv = sigmoidf_(s0 + xg4.x);
                float fv = sigmoidf_(s1 + xg4.y);
                float gv = tanhf_(s2 + xg4.z);
                float ov = sigmoidf_(s3 + xg4.w);
                creg = fv * creg + iv * gv;
                float hv = ov * tanhf_(creg);
                float pub = hv + 2.0f;          // in (1,3): never zero bits
                float* dst = g_hist + (t << 9) + hi;
                asm volatile("st.volatile.global.f32 [%0], %1;"
                             :: "l"(dst), "f"(pub) : "memory");
                h_sm[(t + 1) & 1][hi] = hv;     // own-CTA smem bypass
            }
        } else if (t < SQ - 1 && !mine) {
            // ------------------ poller ------------------
            const float* p = g_hist + (t << 9) + widx;
            unsigned a, b;
            for (;;) {
                asm volatile("ld.volatile.global.v2.u32 {%0,%1}, [%2];"
                             : "=r"(a), "=r"(b) : "l"(p));
                if (a != 0u && b != 0u) break;  // same producer CTA for both
            }
            float* q = &h_sm[(t + 1) & 1][widx];
            q[0] = __uint_as_float(a) - 2.0f;
            q[1] = __uint_as_float(b) - 2.0f;
        }
        __syncthreads();
    }
}

// ---------------------------------------------------------------------------
// Kernel 3: out[s,t] = (hist[s,:]-2) . W_lin[t,:] + b_lin[t]   (1024 outputs)
// ---------------------------------------------------------------------------
__global__ void __launch_bounds__(256) final_linear_kernel(
    const float* __restrict__ Wlin,
    const float* __restrict__ blin,
    float* __restrict__ out)
{
    const int w = threadIdx.x >> 5, l = threadIdx.x & 31;
    const int wi = blockIdx.x * 8 + w;     // 0..1023
    const int s = wi >> 1, tt = wi & 1;
    float acc = 0.f;
    #pragma unroll
    for (int e = l; e < HD; e += 32) {
        float hv = g_hist[(size_t)s * HD + e] - 2.0f;
        acc = fmaf(hv, Wlin[(size_t)tt * HD + e], acc);
    }
    #pragma unroll
    for (int off = 16; off; off >>= 1) acc += __shfl_xor_sync(0xffffffffu, acc, off);
    if (l == 0) out[s * 2 + tt] = acc + blin[tt];
}

// ---------------------------------------------------------------------------
extern "C" void kernel_launch(void* const* d_in, const int* in_sizes, int n_in,
                              void* d_out, int out_size)
{
    const int*   sent = (const int*)d_in[0];            // (64,512) int32/int64 words
    const float* h0   = (const float*)d_in[1];          // (1,64,512)
    const float* c0   = (const float*)d_in[2];          // (1,64,512)
    const float* emb  = (const float*)d_in[3];          // (32000,512)
    const float* Wih  = (const float*)d_in[4];          // (2048,512)
    const float* Whh  = (const float*)d_in[5];          // (2048,512)
    const float* bih  = (const float*)d_in[6];          // (2048,)
    const float* bhh  = (const float*)d_in[7];          // (2048,)
    const float* Wlin = (const float*)d_in[8];          // (2,512)
    const float* blin = (const float*)d_in[9];          // (2,)
    float* out = (float*)d_out;                         // (512,2)

    zero_hist_kernel<<<256, 256>>>();
    token_prep_kernel<<<1, SQ>>>(sent);
    xg_gemm_kernel<<<dim3(SQ / BM, G4 / BN), 256>>>(emb, Wih, bih, bhh);
    lstm_scan_kernel<<<NCTA, TPB>>>(h0, c0, Whh);
    final_linear_kernel<<<128, 256>>>(Wlin, blin, out);
}

// round 10
// speedup vs baseline: 1.4285x; 1.4285x over previous
#include <cuda_runtime.h>
#include <cstddef>

// Problem constants
#define SQ   512      // sequence length S
#define ED   512      // embedding dim E
#define HD   512      // hidden dim H
#define G4   2048     // 4*H gates
#define BSEL 63       // only batch sample 63 reaches the output
#define NVOC 32000

#define NCTA 64       // scan CTAs; each owns 8 h elements
#define TPB  512      // 16 warps

// Scratch (device globals; no allocation allowed)
__device__ float g_hist[SQ * HD];    // published h+2.0 per (t, element); 0 = not ready. 1 MB
__device__ float g_xg[SQ * G4];      // xg TRANSPOSED: [t][element][gate], 4 MB
__device__ int   g_tok[SQ];          // batch-63 tokens, dtype-normalized

// ---------------------------------------------------------------------------
// Kernel 0a: zero the history buffer so graph replays are deterministic.
// ---------------------------------------------------------------------------
__global__ void zero_hist_kernel() {
    int idx = blockIdx.x * blockDim.x + threadIdx.x;
    int stride = gridDim.x * blockDim.x;
    for (int i = idx; i < SQ * HD; i += stride) g_hist[i] = 0.f;
}

// ---------------------------------------------------------------------------
// Kernel 0b: normalize token dtype (int32 vs int64) and extract batch 63.
// ---------------------------------------------------------------------------
__global__ void __launch_bounds__(SQ) token_prep_kernel(const int* __restrict__ raw) {
    __shared__ int any_nz;
    const int tid = threadIdx.x;            // 0..511
    if (tid == 0) any_nz = 0;
    __syncthreads();
    if (tid < 256 && raw[2 * tid + 1] != 0) atomicExch(&any_nz, 1);
    __syncthreads();
    const bool is64 = (any_nz == 0);
    const long long idx = (long long)BSEL * SQ + tid;
    int tok = is64 ? raw[2 * idx] : raw[idx];
    tok = min(max(tok, 0), NVOC - 1);       // never IMA, even on dtype surprise
    g_tok[tid] = tok;
}

// ---------------------------------------------------------------------------
// Kernel 1: xg GEMM, output TRANSPOSED to [t][element][gate] for the scan's
// contiguous float4 per-element bias fetch.
// ---------------------------------------------------------------------------
#define BM 64
#define BN 64
#define BK 16

__global__ void __launch_bounds__(256) xg_gemm_kernel(
    const float* __restrict__ emb,
    const float* __restrict__ Wih,
    const float* __restrict__ bih,
    const float* __restrict__ bhh)
{
    __shared__ float As[BK][BM];
    __shared__ float Bs[BK][BN];
    __shared__ int   toks[BM];

    const int bs = blockIdx.x * BM;   // s base
    const int bg = blockIdx.y * BN;   // g base
    const int tid = threadIdx.x;

    if (tid < BM) toks[tid] = g_tok[bs + tid];
    __syncthreads();

    const int tm = (tid >> 4) << 2;   // 0,4,...,60
    const int tn = (tid & 15) << 2;   // 0,4,...,60

    float acc[4][4];
    #pragma unroll
    for (int i = 0; i < 4; i++)
        #pragma unroll
        for (int j = 0; j < 4; j++) acc[i][j] = 0.f;

    for (int k0 = 0; k0 < ED; k0 += BK) {
        #pragma unroll
        for (int i = tid; i < BM * BK; i += 256) {
            int m = i >> 4, k = i & 15;
            As[k][m] = emb[(size_t)toks[m] * ED + k0 + k];
        }
        #pragma unroll
        for (int i = tid; i < BN * BK; i += 256) {
            int n = i >> 4, k = i & 15;
            Bs[k][n] = Wih[(size_t)(bg + n) * ED + k0 + k];
        }
        __syncthreads();
        #pragma unroll
        for (int k = 0; k < BK; k++) {
            float4 a = *(const float4*)&As[k][tm];
            float4 b = *(const float4*)&Bs[k][tn];
            float av[4] = {a.x, a.y, a.z, a.w};
            float bv[4] = {b.x, b.y, b.z, b.w};
            #pragma unroll
            for (int i = 0; i < 4; i++)
                #pragma unroll
                for (int j = 0; j < 4; j++)
                    acc[i][j] = fmaf(av[i], bv[j], acc[i][j]);
        }
        __syncthreads();
    }

    #pragma unroll
    for (int i = 0; i < 4; i++) {
        int s = bs + tm + i;
        #pragma unroll
        for (int j = 0; j < 4; j++) {
            int g = bg + tn + j;
            int e = g & (HD - 1), q = g >> 9;
            g_xg[(size_t)s * G4 + (e << 2) + q] = acc[i][j] + bih[g] + bhh[g];
        }
    }
}

// ---------------------------------------------------------------------------
// Kernel 2: persistent LSTM scan, batch element 63 only.  (R8 structure.)
// 64 CTAs x 512 threads (16 warps). CTA c owns h elements [8c, 8c+8).
// Warp w computes 2 of the CTA's 32 gate dot-products (each length 512;
// weights in 32 regs/lane). Warp0 lanes 0-7 do activations and publish
// h+2.0f for all 8 elements in ONE coalesced 32B store.
// SYNC IS GPU-SCOPED (ld/st.relaxed.gpu): coherence point = L2, never DRAM.
// (volatile on GB300 compiles to sys scope; with coherent C2C host memory the
//  sys coherence point is memory-side -> every poll was a DRAM round trip,
//  which is what saturated DRAM in the R4/R9 regressions.)
// ---------------------------------------------------------------------------
__device__ __forceinline__ float sigmoidf_(float x) {
    return __fdividef(1.f, 1.f + __expf(-x));
}
__device__ __forceinline__ float tanhf_(float x) {
    x = fminf(fmaxf(x, -15.f), 15.f);
    float e = __expf(2.f * x);
    return __fdividef(e - 1.f, e + 1.f);
}

__global__ void __launch_bounds__(TPB, 1) lstm_scan_kernel(
    const float* __restrict__ h0,
    const float* __restrict__ c0,
    const float* __restrict__ Whh)
{
    __shared__ float h_sm[2][HD];       // parity double-buffered current h (4 KB)
    __shared__ float gexch[32];         // gate pre-activations, indexed q*8+e

    const int cta = blockIdx.x;         // 0..63
    const int tid = threadIdx.x;
    const int w = tid >> 5;             // warp 0..15
    const int l = tid & 31;

    // Warp w owns dots d0=2w, d1=2w+1; d = q*8+e (q=gate 0..3, e=local elem 0..7)
    const int d0 = 2 * w, d1 = 2 * w + 1;
    const int r0 = ((d0 >> 3) << 9) + (cta << 3) + (d0 & 7);   // W_hh row for d0
    const int r1 = ((d1 >> 3) << 9) + (cta << 3) + (d1 & 7);
    float wt0[16], wt1[16];
    #pragma unroll
    for (int a = 0; a < 4; a++) {
        float4 v = *(const float4*)&Whh[((size_t)r0 << 9) + (a << 7) + (l << 2)];
        wt0[a * 4 + 0] = v.x; wt0[a * 4 + 1] = v.y;
        wt0[a * 4 + 2] = v.z; wt0[a * 4 + 3] = v.w;
        float4 u = *(const float4*)&Whh[((size_t)r1 << 9) + (a << 7) + (l << 2)];
        wt1[a * 4 + 0] = u.x; wt1[a * 4 + 1] = u.y;
        wt1[a * 4 + 2] = u.z; wt1[a * 4 + 3] = u.w;
    }

    float creg = 0.f;
    if (w == 0 && l < 8) creg = c0[(size_t)BSEL * HD + (cta << 3) + l];

    // Seed h_sm[0] with h0[0, 63, :] (one element per thread)
    h_sm[0][tid] = h0[(size_t)BSEL * HD + tid];
    __syncthreads();

    for (int t = 0; t < SQ; t++) {
        // Warp0 lanes 0-7: prefetch this step's xg biases (transposed layout,
        // contiguous float4 per element) BEFORE the poll — latency overlapped.
        float4 xg4 = make_float4(0.f, 0.f, 0.f, 0.f);
        if (w == 0 && l < 8)
            xg4 = *(const float4*)&g_xg[((size_t)t << 11) + (((cta << 3) + l) << 2)];

        if (t > 0) {
            // Warp w polls its disjoint 32-element chunk of h(t-1), 1 word/lane.
            // GPU-scoped: hits/misses resolve in L2, never DRAM.
            const float* p = g_hist + ((t - 1) << 9) + (w << 5) + l;
            unsigned a;
            for (;;) {
                asm volatile("ld.relaxed.gpu.global.u32 %0, [%1];" : "=r"(a) : "l"(p));
                if (__all_sync(0xffffffffu, a != 0u)) break;
            }
            h_sm[t & 1][(w << 5) + l] = __uint_as_float(a) - 2.0f;
        }
        __syncthreads();

        // Two 512-length dots (h from smem, W from registers).
        const float* hb = h_sm[t & 1];
        float hreg[16];
        #pragma unroll
        for (int a = 0; a < 4; a++) {
            float4 v = *(const float4*)&hb[(a << 7) + (l << 2)];
            hreg[a * 4 + 0] = v.x; hreg[a * 4 + 1] = v.y;
            hreg[a * 4 + 2] = v.z; hreg[a * 4 + 3] = v.w;
        }
        float s0 = 0.f, s1 = 0.f;
        #pragma unroll
        for (int i = 0; i < 16; i++) {
            s0 = fmaf(wt0[i], hreg[i], s0);
            s1 = fmaf(wt1[i], hreg[i], s1);
        }
        #pragma unroll
        for (int off = 16; off; off >>= 1) {
            s0 += __shfl_xor_sync(0xffffffffu, s0, off);
            s1 += __shfl_xor_sync(0xffffffffu, s1, off);
        }
        if (l == 0) { gexch[d0] = s0; gexch[d1] = s1; }
        __syncthreads();

        // Warp0 lanes 0-7: activations for the CTA's 8 elements + ONE coalesced
        // 32-byte publish (single visibility window for consumers).
        if (w == 0 && l < 8) {
            float gi = gexch[l]      + xg4.x;
            float gf = gexch[8 + l]  + xg4.y;
            float gg = gexch[16 + l] + xg4.z;
            float go = gexch[24 + l] + xg4.w;
            float iv = sigmoidf_(gi);
            float fv = sigmoidf_(gf);
            float gv = tanhf_(gg);
            float ov = sigmoidf_(go);
            creg = fv * creg + iv * gv;
            float hv = ov * tanhf_(creg);
            float pub = hv + 2.0f;          // in (1,3): never zero bits
            float* dst = g_hist + (t << 9) + (cta << 3) + l;
            asm volatile("st.relaxed.gpu.global.f32 [%0], %1;"
                         :: "l"(dst), "f"(pub) : "memory");
        }
        // h_sm is parity double-buffered; the two barriers above bound skew.
    }
}

// ---------------------------------------------------------------------------
// Kernel 3: out[s,t] = (hist[s,:]-2) . W_lin[t,:] + b_lin[t]   (1024 outputs)
// ---------------------------------------------------------------------------
__global__ void __launch_bounds__(256) final_linear_kernel(
    const float* __restrict__ Wlin,
    const float* __restrict__ blin,
    float* __restrict__ out)
{
    const int w = threadIdx.x >> 5, l = threadIdx.x & 31;
    const int wi = blockIdx.x * 8 + w;     // 0..1023
    const int s = wi >> 1, tt = wi & 1;
    float acc = 0.f;
    #pragma unroll
    for (int e = l; e < HD; e += 32) {
        float hv = g_hist[(size_t)s * HD + e] - 2.0f;
        acc = fmaf(hv, Wlin[(size_t)tt * HD + e], acc);
    }
    #pragma unroll
    for (int off = 16; off; off >>= 1) acc += __shfl_xor_sync(0xffffffffu, acc, off);
    if (l == 0) out[s * 2 + tt] = acc + blin[tt];
}

// ---------------------------------------------------------------------------
extern "C" void kernel_launch(void* const* d_in, const int* in_sizes, int n_in,
                              void* d_out, int out_size)
{
    const int*   sent = (const int*)d_in[0];            // (64,512) int32/int64 words
    const float* h0   = (const float*)d_in[1];          // (1,64,512)
    const float* c0   = (const float*)d_in[2];          // (1,64,512)
    const float* emb  = (const float*)d_in[3];          // (32000,512)
    const float* Wih  = (const float*)d_in[4];          // (2048,512)
    const float* Whh  = (const float*)d_in[5];          // (2048,512)
    const float* bih  = (const float*)d_in[6];          // (2048,)
    const float* bhh  = (const float*)d_in[7];          // (2048,)
    const float* Wlin = (const float*)d_in[8];          // (2,512)
    const float* blin = (const float*)d_in[9];          // (2,)
    float* out = (float*)d_out;                         // (512,2)

    zero_hist_kernel<<<256, 256>>>();
    token_prep_kernel<<<1, SQ>>>(sent);
    xg_gemm_kernel<<<dim3(SQ / BM, G4 / BN), 256>>>(emb, Wih, bih, bhh);
    lstm_scan_kernel<<<NCTA, TPB>>>(h0, c0, Whh);
    final_linear_kernel<<<128, 256>>>(Wlin, blin, out);
}

// round 12
// speedup vs baseline: 1.7909x; 1.2537x over previous
#include <cuda_runtime.h>
#include <cstddef>

// Problem constants
#define SQ   512      // sequence length S
#define ED   512      // embedding dim E
#define HD   512      // hidden dim H
#define G4   2048     // 4*H gates
#define BSEL 63       // only batch sample 63 reaches the output
#define NVOC 32000

#define NCTA 64       // scan CTAs; each owns 8 h elements
#define TPB  512      // 16 warps

// Scratch (device globals; no allocation allowed)
__device__ float g_hist[SQ * HD];    // published h+2.0 per (t, element); 0 = not ready. 1 MB
__device__ float g_xg[SQ * G4];      // xg TRANSPOSED: [t][element][gate], 4 MB
__device__ int   g_tok[SQ];          // batch-63 tokens, dtype-normalized

// ---------------------------------------------------------------------------
// Kernel 0a: zero the history buffer so graph replays are deterministic.
// ---------------------------------------------------------------------------
__global__ void zero_hist_kernel() {
    int idx = blockIdx.x * blockDim.x + threadIdx.x;
    int stride = gridDim.x * blockDim.x;
    for (int i = idx; i < SQ * HD; i += stride) g_hist[i] = 0.f;
}

// ---------------------------------------------------------------------------
// Kernel 0b: normalize token dtype (int32 vs int64) and extract batch 63.
// ---------------------------------------------------------------------------
__global__ void __launch_bounds__(SQ) token_prep_kernel(const int* __restrict__ raw) {
    __shared__ int any_nz;
    const int tid = threadIdx.x;            // 0..511
    if (tid == 0) any_nz = 0;
    __syncthreads();
    if (tid < 256 && raw[2 * tid + 1] != 0) atomicExch(&any_nz, 1);
    __syncthreads();
    const bool is64 = (any_nz == 0);
    const long long idx = (long long)BSEL * SQ + tid;
    int tok = is64 ? raw[2 * idx] : raw[idx];
    tok = min(max(tok, 0), NVOC - 1);       // never IMA, even on dtype surprise
    g_tok[tid] = tok;
}

// ---------------------------------------------------------------------------
// Kernel 1: xg GEMM, output TRANSPOSED to [t][element][gate].
// ---------------------------------------------------------------------------
#define BM 64
#define BN 64
#define BK 16

__global__ void __launch_bounds__(256) xg_gemm_kernel(
    const float* __restrict__ emb,
    const float* __restrict__ Wih,
    const float* __restrict__ bih,
    const float* __restrict__ bhh)
{
    __shared__ float As[BK][BM];
    __shared__ float Bs[BK][BN];
    __shared__ int   toks[BM];

    const int bs = blockIdx.x * BM;   // s base
    const int bg = blockIdx.y * BN;   // g base
    const int tid = threadIdx.x;

    if (tid < BM) toks[tid] = g_tok[bs + tid];
    __syncthreads();

    const int tm = (tid >> 4) << 2;   // 0,4,...,60
    const int tn = (tid & 15) << 2;   // 0,4,...,60

    float acc[4][4];
    #pragma unroll
    for (int i = 0; i < 4; i++)
        #pragma unroll
        for (int j = 0; j < 4; j++) acc[i][j] = 0.f;

    for (int k0 = 0; k0 < ED; k0 += BK) {
        #pragma unroll
        for (int i = tid; i < BM * BK; i += 256) {
            int m = i >> 4, k = i & 15;
            As[k][m] = emb[(size_t)toks[m] * ED + k0 + k];
        }
        #pragma unroll
        for (int i = tid; i < BN * BK; i += 256) {
            int n = i >> 4, k = i & 15;
            Bs[k][n] = Wih[(size_t)(bg + n) * ED + k0 + k];
        }
        __syncthreads();
        #pragma unroll
        for (int k = 0; k < BK; k++) {
            float4 a = *(const float4*)&As[k][tm];
            float4 b = *(const float4*)&Bs[k][tn];
            float av[4] = {a.x, a.y, a.z, a.w};
            float bv[4] = {b.x, b.y, b.z, b.w};
            #pragma unroll
            for (int i = 0; i < 4; i++)
                #pragma unroll
                for (int j = 0; j < 4; j++)
                    acc[i][j] = fmaf(av[i], bv[j], acc[i][j]);
        }
        __syncthreads();
    }

    #pragma unroll
    for (int i = 0; i < 4; i++) {
        int s = bs + tm + i;
        #pragma unroll
        for (int j = 0; j < 4; j++) {
            int g = bg + tn + j;
            int e = g & (HD - 1), q = g >> 9;
            g_xg[(size_t)s * G4 + (e << 2) + q] = acc[i][j] + bih[g] + bhh[g];
        }
    }
}

// ---------------------------------------------------------------------------
// Kernel 2: persistent LSTM scan, batch element 63 only.  (R8 base.)
// 64 CTAs x 512 threads (16 warps). CTA c owns h elements [8c, 8c+8).
// SENTINEL POLLING: only warps 12-15 (one per SMSP) poll h(t-1), each lane a
// v4 volatile load covering 4 words of ONE producer's 8-word block; warps
// 0-11 wait at the barrier issuing nothing. This cuts chip-wide poll request
// rate ~16x vs R8 (the variable that ordered all prior regressions).
// Each warp computes 2 of the CTA's 32 gate dots; lane 0 seeds accumulators
// with its xg biases so the warp0 tail is pure activations + ONE coalesced
// 32B volatile publish.
// ---------------------------------------------------------------------------
__device__ __forceinline__ float sigmoidf_(float x) {
    return __fdividef(1.f, 1.f + __expf(-x));
}
__device__ __forceinline__ float tanhf_(float x) {
    x = fminf(fmaxf(x, -15.f), 15.f);
    float e = __expf(2.f * x);
    return __fdividef(e - 1.f, e + 1.f);
}

__global__ void __launch_bounds__(TPB, 1) lstm_scan_kernel(
    const float* __restrict__ h0,
    const float* __restrict__ c0,
    const float* __restrict__ Whh)
{
    __shared__ float h_sm[2][HD];       // parity double-buffered current h (4 KB)
    __shared__ float gexch[32];         // completed gate pre-activations, q*8+e

    const int cta = blockIdx.x;         // 0..63
    const int tid = threadIdx.x;
    const int w = tid >> 5;             // warp 0..15
    const int l = tid & 31;

    // Warp w owns dots d0=2w, d1=2w+1; d = q*8+e (q=gate 0..3, e=local elem 0..7)
    const int d0 = 2 * w, d1 = 2 * w + 1;
    const int r0 = ((d0 >> 3) << 9) + (cta << 3) + (d0 & 7);   // W_hh row for d0
    const int r1 = ((d1 >> 3) << 9) + (cta << 3) + (d1 & 7);
    float wt0[16], wt1[16];
    #pragma unroll
    for (int a = 0; a < 4; a++) {
        float4 v = *(const float4*)&Whh[((size_t)r0 << 9) + (a << 7) + (l << 2)];
        wt0[a * 4 + 0] = v.x; wt0[a * 4 + 1] = v.y;
        wt0[a * 4 + 2] = v.z; wt0[a * 4 + 3] = v.w;
        float4 u = *(const float4*)&Whh[((size_t)r1 << 9) + (a << 7) + (l << 2)];
        wt1[a * 4 + 0] = u.x; wt1[a * 4 + 1] = u.y;
        wt1[a * 4 + 2] = u.z; wt1[a * 4 + 3] = u.w;
    }

    // xg addresses for this warp's two dots (lane 0 only uses them)
    const int e0 = d0 & 7, q0 = d0 >> 3;
    const int e1 = d1 & 7, q1 = d1 >> 3;
    const int xga_off = (((cta << 3) + e0) << 2) + q0;
    const int xgb_off = (((cta << 3) + e1) << 2) + q1;

    float creg = 0.f;
    if (w == 0 && l < 8) creg = c0[(size_t)BSEL * HD + (cta << 3) + l];

    // Seed h_sm[0] with h0[0, 63, :] (one element per thread)
    h_sm[0][tid] = h0[(size_t)BSEL * HD + tid];
    __syncthreads();

    for (int t = 0; t < SQ; t++) {
        // Lane 0 of each warp: prefetch this step's two xg biases (scalar,
        // same 128B line CTA-wide) before the poll/barrier — overlapped.
        float xga = 0.f, xgb = 0.f;
        if (l == 0) {
            xga = g_xg[((size_t)t << 11) + xga_off];
            xgb = g_xg[((size_t)t << 11) + xgb_off];
        }

        if (t > 0 && w >= 12) {
            // Sentinel warps (one per SMSP): lane covers 4 contiguous words of
            // h(t-1) — all from ONE producer CTA's 8-word block (base%8 in {0,4}).
            const int base = ((w - 12) << 7) + (l << 2);
            const float* p = g_hist + ((t - 1) << 9) + base;
            unsigned a, b, c, d;
            for (;;) {
                asm volatile("ld.volatile.global.v4.u32 {%0,%1,%2,%3}, [%4];"
                             : "=r"(a), "=r"(b), "=r"(c), "=r"(d) : "l"(p));
                if (a != 0u && b != 0u && c != 0u && d != 0u) break;
            }
            float* q = &h_sm[t & 1][base];
            q[0] = __uint_as_float(a) - 2.0f;
            q[1] = __uint_as_float(b) - 2.0f;
            q[2] = __uint_as_float(c) - 2.0f;
            q[3] = __uint_as_float(d) - 2.0f;
        }
        __syncthreads();

        // Two 512-length dots (h from smem, W from registers).
        const float* hb = h_sm[t & 1];
        float hreg[16];
        #pragma unroll
        for (int a = 0; a < 4; a++) {
            float4 v = *(const float4*)&hb[(a << 7) + (l << 2)];
            hreg[a * 4 + 0] = v.x; hreg[a * 4 + 1] = v.y;
            hreg[a * 4 + 2] = v.z; hreg[a * 4 + 3] = v.w;
        }
        float s0 = xga, s1 = xgb;       // lane0 seeds with xg; others zero
        #pragma unroll
        for (int i = 0; i < 16; i++) {
            s0 = fmaf(wt0[i], hreg[i], s0);
            s1 = fmaf(wt1[i], hreg[i], s1);
        }
        #pragma unroll
        for (int off = 16; off; off >>= 1) {
            s0 += __shfl_xor_sync(0xffffffffu, s0, off);
            s1 += __shfl_xor_sync(0xffffffffu, s1, off);
        }
        if (l == 0) { gexch[d0] = s0; gexch[d1] = s1; }
        __syncthreads();

        // Warp0 lanes 0-7: pure activations + ONE coalesced 32B publish.
        if (w == 0 && l < 8) {
            float iv = sigmoidf_(gexch[l]);
            float fv = sigmoidf_(gexch[8 + l]);
            float gv = tanhf_(gexch[16 + l]);
            float ov = sigmoidf_(gexch[24 + l]);
            creg = fv * creg + iv * gv;
            float hv = ov * tanhf_(creg);
            float pub = hv + 2.0f;          // in (1,3): never zero bits
            float* dst = g_hist + (t << 9) + (cta << 3) + l;
            asm volatile("st.volatile.global.f32 [%0], %1;"
                         :: "l"(dst), "f"(pub) : "memory");
        }
        // h_sm is parity double-buffered; the two barriers above bound skew.
    }
}

// ---------------------------------------------------------------------------
// Kernel 3: out[s,t] = (hist[s,:]-2) . W_lin[t,:] + b_lin[t]   (1024 outputs)
// ---------------------------------------------------------------------------
__global__ void __launch_bounds__(256) final_linear_kernel(
    const float* __restrict__ Wlin,
    const float* __restrict__ blin,
    float* __restrict__ out)
{
    const int w = threadIdx.x >> 5, l = threadIdx.x & 31;
    const int wi = blockIdx.x * 8 + w;     // 0..1023
    const int s = wi >> 1, tt = wi & 1;
    float acc = 0.f;
    #pragma unroll
    for (int e = l; e < HD; e += 32) {
        float hv = g_hist[(size_t)s * HD + e] - 2.0f;
        acc = fmaf(hv, Wlin[(size_t)tt * HD + e], acc);
    }
    #pragma unroll
    for (int off = 16; off; off >>= 1) acc += __shfl_xor_sync(0xffffffffu, acc, off);
    if (l == 0) out[s * 2 + tt] = acc + blin[tt];
}

// ---------------------------------------------------------------------------
extern "C" void kernel_launch(void* const* d_in, const int* in_sizes, int n_in,
                              void* d_out, int out_size)
{
    const int*   sent = (const int*)d_in[0];            // (64,512) int32/int64 words
    const float* h0   = (const float*)d_in[1];          // (1,64,512)
    const float* c0   = (const float*)d_in[2];          // (1,64,512)
    const float* emb  = (const float*)d_in[3];          // (32000,512)
    const float* Wih  = (const float*)d_in[4];          // (2048,512)
    const float* Whh  = (const float*)d_in[5];          // (2048,512)
    const float* bih  = (const float*)d_in[6];          // (2048,)
    const float* bhh  = (const float*)d_in[7];          // (2048,)
    const float* Wlin = (const float*)d_in[8];          // (2,512)
    const float* blin = (const float*)d_in[9];          // (2,)
    float* out = (float*)d_out;                         // (512,2)

    zero_hist_kernel<<<256, 256>>>();
    token_prep_kernel<<<1, SQ>>>(sent);
    xg_gemm_kernel<<<dim3(SQ / BM, G4 / BN), 256>>>(emb, Wih, bih, bhh);
    lstm_scan_kernel<<<NCTA, TPB>>>(h0, c0, Whh);
    final_linear_kernel<<<128, 256>>>(Wlin, blin, out);
}